// round 12
// baseline (speedup 1.0000x reference)
#include <cuda_runtime.h>
#include <math.h>

#define B_    512
#define T_    8
#define H_    512
#define K1PAD 544
#define NCTA  512
#define NTHR  128

#define BM  32
#define BN  32
#define BK  32
#define SST 36                      // 32 + 4 pad words (row stride 144B)
#define STAGES 3
#define STG_W ((BM + BN) * SST)     // 2304 words per stage (A then B)

// ---------------- scratch (static device globals; no allocation) ----------------
__device__ float g_a1[B_ * K1PAD];        // ODE GEMM1 input, tf32 values
__device__ float g_z1[B_ * 1024];         // tf32 values
__device__ float g_z2[B_ * 1024];         // tf32 values
__device__ float g_ks[B_ * H_];           // RK weighted sum, fp32
__device__ float g_h [B_ * H_];           // hidden state, fp32
__device__ float g_gi[B_ * T_ * 1536];    // precomputed input gates, fp32
__device__ float g_gh[B_ * 1536];         // hidden gates, fp32
__device__ float g_W1p [1024 * K1PAD];    // weights, tf32 values
__device__ float g_W2t [1024 * 1024];
__device__ float g_W3t [H_ * 1024];
__device__ float g_Whht[1536 * H_];
__device__ float g_Wiht[1536 * H_];
__device__ float g_Woutt[128 * H_];
__device__ float g_xt[B_ * T_ * H_];      // x converted to tf32
__device__ unsigned g_grp[32 * 32];       // tree-barrier group counters, 128B apart
__device__ unsigned g_root;               // tree-barrier root counter
__device__ volatile unsigned g_gen;       // published generation

// ---------------- helpers ----------------
__device__ __forceinline__ unsigned f2tf(float f) {
    unsigned u;
    asm("cvt.rna.tf32.f32 %0, %1;" : "=r"(u) : "f"(f));
    return u;
}

__device__ __forceinline__ void mma8(float* c, const unsigned* a, const unsigned* b) {
    asm volatile(
        "mma.sync.aligned.m16n8k8.row.col.f32.tf32.tf32.f32 "
        "{%0,%1,%2,%3}, {%4,%5,%6,%7}, {%8,%9}, {%0,%1,%2,%3};"
        : "+f"(c[0]), "+f"(c[1]), "+f"(c[2]), "+f"(c[3])
        : "r"(a[0]), "r"(a[1]), "r"(a[2]), "r"(a[3]), "r"(b[0]), "r"(b[1]));
}

__device__ __forceinline__ void ldsm4(unsigned& r0, unsigned& r1,
                                      unsigned& r2, unsigned& r3, unsigned addr) {
    asm volatile("ldmatrix.sync.aligned.m8n8.x4.shared.b16 {%0,%1,%2,%3}, [%4];"
                 : "=r"(r0), "=r"(r1), "=r"(r2), "=r"(r3) : "r"(addr));
}

__device__ __forceinline__ void cpa16(unsigned d, const float* s) {
    asm volatile("cp.async.cg.shared.global [%0], [%1], 16;" :: "r"(d), "l"(s));
}
__device__ __forceinline__ void cpcommit() { asm volatile("cp.async.commit_group;"); }

// Two-level tree grid barrier for 512 CTAs: 32 groups of 16 (separate 128B
// lines -> parallel LTS slices), root collects 32. All counters MONOTONIC
// (no resets) -> replay-safe exactly like the validated R8 design.
__device__ __forceinline__ void grid_bar(unsigned target, int bid) {
    __syncthreads();
    __threadfence();
    __syncthreads();
    if (threadIdx.x == 0) {
        unsigned a = atomicAdd(&g_grp[(bid & 31) * 32], 1u);
        if ((a & 15u) == 15u) {                 // last arriver in this group of 16
            unsigned r = atomicAdd(&g_root, 1u);
            if ((r & 31u) == 31u) {             // last of the 32 groups
                __threadfence();
                g_gen = target;
            }
        }
        while ((int)(g_gen - target) < 0) __nanosleep(32);
        __threadfence();
    }
    __syncthreads();
}

// ---------------- GEMM phase (persistent-kernel device function) ----------------
// C-tile = A[M,K] @ Wt[N,K]^T + bias, operands already tf32 in gmem.
// 32x32 CTA tile, 4 warps each 16x16 (wm = warp>>1 row-half, wn = warp&1
// col-half). 3-stage cp.async pipeline; fragments loaded via ldmatrix.x4
// (lane mapping reproduces the validated m16n8k8 tf32 fragment layout).
template<typename F>
__device__ __forceinline__ void gemm_tiles(
    const float* __restrict__ A, int lda,
    const float* __restrict__ Wt,
    const float* __restrict__ bias,
    int N, int K, int ntiles,
    unsigned smu, F epi)
{
    const int tid  = threadIdx.x;
    const int lane = tid & 31, warp = tid >> 5;
    const int wm = warp >> 1, wn = warp & 1;
    const int g = lane >> 2, tg = lane & 3;
    const int ncol = N / BN;
    const int nch  = K / BK;

    // ldmatrix per-lane byte offsets (relative to stage base), constant per tile:
    // A (x4 = [rows0-7,kLo][rows8-15,kLo][rows0-7,kHi][rows8-15,kHi]):
    //   lanes 0-15 -> rows wm*16+(lane&15), kLo; lanes 16-31 -> same rows, kHi
    const unsigned aoff = (unsigned)((wm * 16 + (lane & 15)) * (SST * 4)
                                     + (lane >> 4) * 16);
    // B (x4 = [n0-7,kLo][n0-7,kHi][n8-15,kLo][n8-15,kHi] within this warp's
    //    16-wide n strip): row = wn*16 + (lane>>4)*8 + (lane&7), half=(lane>>3)&1
    const unsigned boff = (unsigned)((BM + wn * 16 + (lane >> 4) * 8 + (lane & 7))
                                     * (SST * 4) + ((lane >> 3) & 1) * 16);

    for (int tile = blockIdx.x; tile < ntiles; tile += NCTA) {
        const int row0 = (tile / ncol) * BM;
        const int col0 = (tile % ncol) * BN;
        const float* Ab = A  + (size_t)row0 * lda;
        const float* Bb = Wt + (size_t)col0 * K;
        __syncthreads();   // previous tile's smem reads complete

        auto issue = [&](int ck, int st) {
            unsigned base = smu + (unsigned)(st * STG_W) * 4u;
            int k0 = ck * BK;
#pragma unroll
            for (int i = 0; i < 2; i++) {   // A: 32x32 = 256 float4, 2/thread
                int lin = tid + i * NTHR; int r = lin >> 3, c4 = (lin & 7) * 4;
                cpa16(base + (unsigned)(r * SST + c4) * 4u,
                      Ab + (size_t)r * lda + k0 + c4);
            }
#pragma unroll
            for (int i = 0; i < 2; i++) {   // B: 32x32 = 256 float4, 2/thread
                int lin = tid + i * NTHR; int r = lin >> 3, c4 = (lin & 7) * 4;
                cpa16(base + (unsigned)((BM + r) * SST + c4) * 4u,
                      Bb + (size_t)r * K + k0 + c4);
            }
        };

        // pipeline prologue: chunks 0 and 1 (always 2 commits)
        issue(0, 0); cpcommit();
        if (nch > 1) issue(1, 1);
        cpcommit();

        float acc[2][4];
#pragma unroll
        for (int b = 0; b < 2; b++)
#pragma unroll
            for (int e = 0; e < 4; e++) acc[b][e] = 0.f;

        for (int ch = 0; ch < nch; ++ch) {
            // retire chunk ch; keep ch+1 in flight
            asm volatile("cp.async.wait_group 1;" ::: "memory");
            __syncthreads();
            if (ch + 2 < nch) issue(ch + 2, (ch + 2) % STAGES);
            cpcommit();     // always commit so pending count stays aligned

            unsigned sbase = smu + (unsigned)((ch % STAGES) * STG_W) * 4u;
#pragma unroll
            for (int ks = 0; ks < 4; ks++) {
                unsigned af[4], b0, b1, b2, b3;
                ldsm4(af[0], af[1], af[2], af[3], sbase + aoff + ks * 32);
                ldsm4(b0, b1, b2, b3,             sbase + boff + ks * 32);
                unsigned bl[2] = {b0, b1}, bh[2] = {b2, b3};
                mma8(acc[0], af, bl);
                mma8(acc[1], af, bh);
            }
        }

#pragma unroll
        for (int nt = 0; nt < 2; nt++)
#pragma unroll
            for (int e = 0; e < 4; e++) {
                int r = row0 + wm * 16 + g + ((e >= 2) ? 8 : 0);
                int c = col0 + wn * 16 + nt * 8 + tg * 2 + (e & 1);
                epi(r, c, acc[nt][e] + bias[c]);
            }
    }
}

// ---------------- the persistent kernel ----------------
__global__ void __launch_bounds__(NTHR, 4)
ode_persist(const float* __restrict__ ts,  const float* __restrict__ bih,
            const float* __restrict__ bhh, const float* __restrict__ b1,
            const float* __restrict__ b2,  const float* __restrict__ b3,
            const float* __restrict__ bout, float* __restrict__ dout)
{
    __shared__ unsigned smem[STAGES * STG_W];     // 27648 bytes
    const unsigned smu = (unsigned)__cvta_generic_to_shared(smem);
    const int tid = threadIdx.x, bid = blockIdx.x;

    unsigned barn = 0, barbase = 0;
    if (tid == 0) barbase = g_gen;   // stable: cannot advance before all CTAs arrive at bar 1

    // ---- phase 0: gi = x @ Wih^T + bih (all 8 steps at once) ----
    gemm_tiles(g_xt, 512, g_Wiht, bih, 1536, 512, (4096 / BM) * (1536 / BN),
               smu,
               [&](int r, int c, float v) { g_gi[(size_t)r * 1536 + c] = v; });
    barn++; grid_bar(barbase + barn, bid);

    for (int tt = 0; tt < T_; tt++) {
        for (int s = 0; s < 4; s++) {
            for (int j = 0; j < 4; j++) {
                // G1: z1 = tf32(swish(a1 @ W1p^T + b1)),  512 tiles
                gemm_tiles(g_a1, K1PAD, g_W1p, b1, 1024, K1PAD, 512,
                           smu,
                           [&](int r, int c, float v) {
                               float sw = v / (1.f + __expf(-v));
                               g_z1[(size_t)r * 1024 + c] = __uint_as_float(f2tf(sw));
                           });
                barn++; grid_bar(barbase + barn, bid);

                // G2: z2 = tf32(swish(z1 @ W2^T + b2)),  512 tiles
                gemm_tiles(g_z1, 1024, g_W2t, b2, 1024, 1024, 512,
                           smu,
                           [&](int r, int c, float v) {
                               float sw = v / (1.f + __expf(-v));
                               g_z2[(size_t)r * 1024 + c] = __uint_as_float(f2tf(sw));
                           });
                barn++; grid_bar(barbase + barn, bid);

                // G3: k = z2 @ W3^T + b3 with fused RK accumulation AND
                // construction of the next eval's A1 = tf32(h + c_next*dt*k).
                // 256 tiles: CTAs 0..255 own fixed 32x32 blocks of h/ks.
                gemm_tiles(g_z2, 1024, g_W3t, b3, H_, 1024, 256,
                           smu,
                           [&](int r, int c, float v) {
                               float t1 = ts[r * T_ + tt];
                               float t0 = (tt == 0) ? ts[r * T_] : ts[r * T_ + tt - 1];
                               float dt = (t1 - t0) * 0.25f;
                               int off = r * H_ + c;
                               float a1v;
                               if (j == 0)      { g_ks[off] = v;        a1v = g_h[off] + 0.5f * dt * v; }
                               else if (j == 1) { g_ks[off] += 2.f * v; a1v = g_h[off] + 0.5f * dt * v; }
                               else if (j == 2) { g_ks[off] += 2.f * v; a1v = g_h[off] + dt * v; }
                               else {
                                   float hn = g_h[off] + dt * (1.f / 6.f) * (g_ks[off] + v);
                                   g_h[off] = hn;
                                   a1v = hn;
                               }
                               g_a1[r * K1PAD + c] = __uint_as_float(f2tf(a1v));
                           });
                // idle CTAs write the next eval's t-column
                if (bid >= 256 && bid < 260) {
                    int r = (bid - 256) * NTHR + tid;
                    float t1 = ts[r * T_ + tt];
                    float t0 = (tt == 0) ? ts[r * T_] : ts[r * T_ + tt - 1];
                    float dt = (t1 - t0) * 0.25f;
                    float sn = (j < 2) ? ((float)s + 0.5f) : ((float)s + 1.f);
                    g_a1[r * K1PAD + 512] = __uint_as_float(f2tf(t0 + sn * dt));
                }
                barn++; grid_bar(barbase + barn, bid);
            }
        }

        // GRU: gh = h @ Whh^T + bhh  (A = a1 which holds tf32(h_ode))
        gemm_tiles(g_a1, K1PAD, g_Whht, bhh, 1536, 512, (512 / BM) * (1536 / BN),
                   smu,
                   [&](int r, int c, float v) { g_gh[(size_t)r * 1536 + c] = v; });
        barn++; grid_bar(barbase + barn, bid);

        // gate: partition matches G3 tile ownership (bid<256 -> 32x32 block)
        // so g_h stays CTA-local. At the last step, write the h output
        // region of dout DIRECTLY from registers (validated in R7/R8).
        if (bid < 256) {
            int r0 = (bid >> 4) * 32, c0 = (bid & 15) * 32;
            for (int e = tid; e < 32 * 32; e += NTHR) {
                int r = r0 + (e >> 5), c = c0 + (e & 31);
                int off = r * H_ + c;
                size_t gio = ((size_t)(r * T_ + tt)) * 1536 + c;
                float ir  = __ldcg(&g_gi[gio]);
                float iz  = __ldcg(&g_gi[gio + 512]);
                float inn = __ldcg(&g_gi[gio + 1024]);
                size_t gho = (size_t)r * 1536 + c;
                float hr = __ldcg(&g_gh[gho]);
                float hz = __ldcg(&g_gh[gho + 512]);
                float hn = __ldcg(&g_gh[gho + 1024]);
                float hv = g_h[off];
                float rg = 1.f / (1.f + expf(-(ir + hr)));
                float zg = 1.f / (1.f + expf(-(iz + hz)));
                float ng = tanhf(inn + rg * hn);
                float h2 = (1.f - zg) * ng + zg * hv;
                g_h[off] = h2;
                g_a1[r * K1PAD + c] = __uint_as_float(f2tf(h2));
                if (tt == T_ - 1) dout[B_ * 128 + off] = h2;   // h output, direct
            }
        }
        if (bid >= 256 && bid < 260) {   // t-column for next time step
            int r = (bid - 256) * NTHR + tid;
            g_a1[r * K1PAD + 512] = __uint_as_float(f2tf(ts[r * T_ + tt]));
        }
        barn++; grid_bar(barbase + barn, bid);
    }

    // outputs: outs[-1] = h @ Wout^T + bout (reads a1 = tf32(h_final)).
    // c output (zeros) is handled by the prologue.
    gemm_tiles(g_a1, K1PAD, g_Woutt, bout, 128, 512, (512 / BM) * (128 / BN),
               smu,
               [&](int r, int c, float v) { dout[(size_t)r * 128 + c] = v; });
}

// ---------------- prologue: exactly 3 kernels so ode_persist is our launch
// #4 (== overall #6; ncu -s 5 -c 1 captures it — worked in R11). ----------------
__global__ void prep_a(const float* __restrict__ x,  float* __restrict__ xt,
                       const float* __restrict__ Wih, float* __restrict__ wih,
                       const float* __restrict__ Whh, float* __restrict__ whh) {
    int i = blockIdx.x * blockDim.x + threadIdx.x;
    if (i < B_ * T_ * H_) xt[i]  = __uint_as_float(f2tf(x[i]));
    if (i < 1536 * H_)    wih[i] = __uint_as_float(f2tf(Wih[i]));
    if (i < 1536 * H_)    whh[i] = __uint_as_float(f2tf(Whh[i]));
}

__global__ void prep_b(const float* __restrict__ W2,  float* __restrict__ w2,
                       const float* __restrict__ W3,  float* __restrict__ w3,
                       const float* __restrict__ Wout, float* __restrict__ wout,
                       const float* __restrict__ W1,  float* __restrict__ w1p) {
    int i = blockIdx.x * blockDim.x + threadIdx.x;
    if (i < 1024 * 1024) w2[i]  = __uint_as_float(f2tf(W2[i]));
    if (i < H_ * 1024)   w3[i]  = __uint_as_float(f2tf(W3[i]));
    if (i < 128 * H_)    wout[i] = __uint_as_float(f2tf(Wout[i]));
    if (i < 1024 * K1PAD) {
        int r = i / K1PAD, c = i - r * K1PAD;
        w1p[i] = (c < H_ + 1) ? __uint_as_float(f2tf(W1[r * (H_ + 1) + c])) : 0.f;
    }
}

__global__ void prep_c(const float* __restrict__ ts, float* __restrict__ dout) {
    int i = blockIdx.x * blockDim.x + threadIdx.x;
    if (i < B_ * H_) {
        g_h[i] = 0.f;
        dout[B_ * 128 + B_ * H_ + i] = 0.f;   // c output: always zeros
    }
    if (i < B_ * K1PAD) {
        int r = i / K1PAD, c = i - r * K1PAD;
        g_a1[i] = (c == 512) ? __uint_as_float(f2tf(ts[r * T_])) : 0.f;
    }
}

// ---------------- driver ----------------
extern "C" void kernel_launch(void* const* d_in, const int* in_sizes, int n_in,
                              void* d_out, int out_size) {
    const float* x    = (const float*)d_in[0];
    const float* ts   = (const float*)d_in[1];
    const float* Wih  = (const float*)d_in[2];
    const float* Whh  = (const float*)d_in[3];
    const float* bih  = (const float*)d_in[4];
    const float* bhh  = (const float*)d_in[5];
    const float* Wout = (const float*)d_in[6];
    const float* bout = (const float*)d_in[7];
    const float* W1   = (const float*)d_in[8];
    const float* b1   = (const float*)d_in[9];
    const float* W2   = (const float*)d_in[10];
    const float* b2   = (const float*)d_in[11];
    const float* W3   = (const float*)d_in[12];
    const float* b3   = (const float*)d_in[13];
    float* dout = (float*)d_out;
    (void)in_sizes; (void)n_in; (void)out_size;

    float *p_xt, *p_wih, *p_whh, *p_w2, *p_w3, *p_wout, *p_w1p;
    cudaGetSymbolAddress((void**)&p_xt,   g_xt);
    cudaGetSymbolAddress((void**)&p_wih,  g_Wiht);
    cudaGetSymbolAddress((void**)&p_whh,  g_Whht);
    cudaGetSymbolAddress((void**)&p_w2,   g_W2t);
    cudaGetSymbolAddress((void**)&p_w3,   g_W3t);
    cudaGetSymbolAddress((void**)&p_wout, g_Woutt);
    cudaGetSymbolAddress((void**)&p_w1p,  g_W1p);

    cudaFuncSetAttribute(ode_persist,
                         cudaFuncAttributePreferredSharedMemoryCarveout, 100);

    prep_a<<<(B_ * T_ * H_ + 255) / 256, 256>>>(x, p_xt, Wih, p_wih, Whh, p_whh);
    prep_b<<<(1024 * 1024 + 255) / 256, 256>>>(W2, p_w2, W3, p_w3,
                                               Wout, p_wout, W1, p_w1p);
    prep_c<<<(B_ * K1PAD + 255) / 256, 256>>>(ts, dout);

    ode_persist<<<NCTA, NTHR>>>(ts, bih, bhh, b1, b2, b3, bout, dout);
}

// round 13
// speedup vs baseline: 1.4308x; 1.4308x over previous
#include <cuda_runtime.h>
#include <math.h>

#define B_    512
#define T_    8
#define H_    512
#define K1PAD 544
#define NCTA  128
#define NTHR  256

#define BM  64
#define BK  32
#define SST 36                      // 32 + 4 pad words (row stride 144B)
#define STAGES 3
#define STG_W ((BM + 64) * SST)     // stage layout sized for BN=64 (A then B)
#define SMEM_BYTES (STAGES * STG_W * 4)   // 55296

// ---------------- scratch (static device globals; no allocation) ----------------
__device__ float g_a1[B_ * K1PAD];        // ODE GEMM1 input, tf32 values
__device__ float g_z1[B_ * 1024];         // tf32 values
__device__ float g_z2[B_ * 1024];         // tf32 values
__device__ float g_ks[B_ * H_];           // RK weighted sum, fp32
__device__ float g_h [B_ * H_];           // hidden state, fp32
__device__ float g_gi[B_ * T_ * 1536];    // precomputed input gates, fp32
__device__ float g_gh[B_ * 1536];         // hidden gates, fp32
__device__ float g_W1p [1024 * K1PAD];    // weights, tf32 values
__device__ float g_W2t [1024 * 1024];
__device__ float g_W3t [H_ * 1024];
__device__ float g_Whht[1536 * H_];
__device__ float g_Wiht[1536 * H_];
__device__ float g_Woutt[128 * H_];
__device__ float g_xt[B_ * T_ * H_];      // x converted to tf32
__device__ unsigned g_grp[16 * 32];       // tree-barrier group counters, 128B apart
__device__ unsigned g_root;               // tree-barrier root counter
__device__ volatile unsigned g_gen;       // published generation

// ---------------- helpers ----------------
__device__ __forceinline__ unsigned f2tf(float f) {
    unsigned u;
    asm("cvt.rna.tf32.f32 %0, %1;" : "=r"(u) : "f"(f));
    return u;
}

__device__ __forceinline__ void mma8(float* c, const unsigned* a, const unsigned* b) {
    asm volatile(
        "mma.sync.aligned.m16n8k8.row.col.f32.tf32.tf32.f32 "
        "{%0,%1,%2,%3}, {%4,%5,%6,%7}, {%8,%9}, {%0,%1,%2,%3};"
        : "+f"(c[0]), "+f"(c[1]), "+f"(c[2]), "+f"(c[3])
        : "r"(a[0]), "r"(a[1]), "r"(a[2]), "r"(a[3]), "r"(b[0]), "r"(b[1]));
}

__device__ __forceinline__ void cpa16(unsigned d, const float* s) {
    asm volatile("cp.async.cg.shared.global [%0], [%1], 16;" :: "r"(d), "l"(s));
}
__device__ __forceinline__ void cpcommit() { asm volatile("cp.async.commit_group;"); }

// Two-level tree grid barrier for 128 CTAs: 16 groups of 8 (separate 128B
// lines -> parallel LTS slices), root collects 16. All counters MONOTONIC
// (no resets) -> replay-safe exactly like the validated R8 design.
__device__ __forceinline__ void grid_bar(unsigned target, int bid) {
    __syncthreads();
    __threadfence();
    __syncthreads();
    if (threadIdx.x == 0) {
        unsigned a = atomicAdd(&g_grp[(bid & 15) * 32], 1u);
        if ((a & 7u) == 7u) {                   // last arriver in this group of 8
            unsigned r = atomicAdd(&g_root, 1u);
            if ((r & 15u) == 15u) {             // last of the 16 groups
                __threadfence();
                g_gen = target;
            }
        }
        while ((int)(g_gen - target) < 0) __nanosleep(32);
        __threadfence();
    }
    __syncthreads();
}

// ---------------- GEMM phase (persistent-kernel device function) ----------------
// C-tile = A[M,K] @ Wt[N,K]^T + bias, operands already tf32 in gmem.
// 64xBN_ CTA tile (BN_ = 64 or 32), 256 threads = 8 warps:
//   BN_=64: 2 (row) x 4 (col) warps, each 32 rows x 16 cols
//   BN_=32: 4 (row) x 2 (col) warps, each 16 rows x 16 cols
// 3-stage cp.async pipeline (validated R10 schedule), scalar-LDS fragment
// loads (validated R8 pattern).
template<int BN_, typename F>
__device__ __forceinline__ void gemm_tiles(
    const float* __restrict__ A, int lda,
    const float* __restrict__ Wt,
    const float* __restrict__ bias,
    int N, int K, int ntiles,
    const unsigned* sm, unsigned smu, F epi)
{
    constexpr int NCOLW = BN_ / 16;       // 4 or 2
    constexpr int NROWW = 8 / NCOLW;      // 2 or 4
    constexpr int RSPAN = BM / NROWW;     // 32 or 16
    constexpr int MT    = RSPAN / 16;     // 2 or 1
    constexpr int BITER = BN_ / 32;       // B float4 loads per thread: 2 or 1

    const int tid  = threadIdx.x;
    const int lane = tid & 31, warp = tid >> 5;
    const int wr = warp / NCOLW, wc = warp % NCOLW;
    const int g = lane >> 2, tg = lane & 3;
    const int ncol = N / BN_;
    const int nch  = K / BK;

    for (int tile = blockIdx.x; tile < ntiles; tile += NCTA) {
        const int row0 = (tile / ncol) * BM;
        const int col0 = (tile % ncol) * BN_;
        const float* Ab = A  + (size_t)row0 * lda;
        const float* Bb = Wt + (size_t)col0 * K;
        __syncthreads();   // previous tile's smem reads complete

        auto issue = [&](int ck, int st) {
            unsigned base = smu + (unsigned)(st * STG_W) * 4u;
            int k0 = ck * BK;
#pragma unroll
            for (int i = 0; i < 2; i++) {   // A: 64x32 = 512 float4, 2/thread
                int lin = tid + i * NTHR; int r = lin >> 3, c4 = (lin & 7) * 4;
                cpa16(base + (unsigned)(r * SST + c4) * 4u,
                      Ab + (size_t)r * lda + k0 + c4);
            }
#pragma unroll
            for (int i = 0; i < BITER; i++) {  // B: BN_x32 float4
                int lin = tid + i * NTHR; int r = lin >> 3, c4 = (lin & 7) * 4;
                cpa16(base + (unsigned)((BM + r) * SST + c4) * 4u,
                      Bb + (size_t)r * K + k0 + c4);
            }
        };

        // pipeline prologue: chunks 0 and 1 (always 2 commits)
        issue(0, 0); cpcommit();
        if (nch > 1) issue(1, 1);
        cpcommit();

        float acc[2][2][4];
#pragma unroll
        for (int a = 0; a < 2; a++)
#pragma unroll
            for (int b = 0; b < 2; b++)
#pragma unroll
                for (int e = 0; e < 4; e++) acc[a][b][e] = 0.f;

        for (int ch = 0; ch < nch; ++ch) {
            // retire chunk ch; keep ch+1 in flight
            asm volatile("cp.async.wait_group 1;" ::: "memory");
            __syncthreads();
            if (ch + 2 < nch) issue(ch + 2, (ch + 2) % STAGES);
            cpcommit();     // always commit so pending count stays aligned

            const unsigned* a_ = sm + (ch % STAGES) * STG_W;
            const unsigned* b_ = a_ + BM * SST;
#pragma unroll
            for (int ks = 0; ks < 4; ks++) {
                unsigned af[MT][4];
#pragma unroll
                for (int mt = 0; mt < MT; mt++) {
                    int r = wr * RSPAN + mt * 16 + g;
                    int base = r * SST + ks * 8 + tg;
                    af[mt][0] = a_[base];
                    af[mt][1] = a_[base + 8 * SST];
                    af[mt][2] = a_[base + 4];
                    af[mt][3] = a_[base + 8 * SST + 4];
                }
#pragma unroll
                for (int nt = 0; nt < 2; nt++) {
                    int n = wc * 16 + nt * 8 + g;
                    unsigned bf[2];
                    bf[0] = b_[n * SST + ks * 8 + tg];
                    bf[1] = b_[n * SST + ks * 8 + tg + 4];
#pragma unroll
                    for (int mt = 0; mt < MT; mt++)
                        mma8(acc[mt][nt], af[mt], bf);
                }
            }
        }

#pragma unroll
        for (int mt = 0; mt < MT; mt++)
#pragma unroll
            for (int nt = 0; nt < 2; nt++)
#pragma unroll
                for (int e = 0; e < 4; e++) {
                    int r = row0 + wr * RSPAN + mt * 16 + g + ((e >= 2) ? 8 : 0);
                    int c = col0 + wc * 16 + nt * 8 + tg * 2 + (e & 1);
                    epi(r, c, acc[mt][nt][e] + bias[c]);
                }
    }
}

// ---------------- the persistent kernel ----------------
__global__ void __launch_bounds__(NTHR, 1)
ode_persist(const float* __restrict__ ts,  const float* __restrict__ bih,
            const float* __restrict__ bhh, const float* __restrict__ b1,
            const float* __restrict__ b2,  const float* __restrict__ b3,
            const float* __restrict__ bout, float* __restrict__ dout)
{
    extern __shared__ unsigned smem[];
    const unsigned smu = (unsigned)__cvta_generic_to_shared(smem);
    const unsigned* sm = smem;
    const int tid = threadIdx.x, bid = blockIdx.x;

    unsigned barn = 0, barbase = 0;
    if (tid == 0) barbase = g_gen;   // stable: cannot advance before all CTAs arrive at bar 1

    // ---- phase 0: gi = x @ Wih^T + bih (all 8 steps at once) ----
    gemm_tiles<64>(g_xt, 512, g_Wiht, bih, 1536, 512, (4096 / BM) * (1536 / 64),
                   sm, smu,
                   [&](int r, int c, float v) { g_gi[(size_t)r * 1536 + c] = v; });
    barn++; grid_bar(barbase + barn, bid);

    for (int tt = 0; tt < T_; tt++) {
        for (int s = 0; s < 4; s++) {
            for (int j = 0; j < 4; j++) {
                // G1: z1 = tf32(swish(a1 @ W1p^T + b1)),  128 tiles (8x16)
                gemm_tiles<64>(g_a1, K1PAD, g_W1p, b1, 1024, K1PAD, 128,
                               sm, smu,
                               [&](int r, int c, float v) {
                                   float sw = v / (1.f + __expf(-v));
                                   g_z1[(size_t)r * 1024 + c] = __uint_as_float(f2tf(sw));
                               });
                barn++; grid_bar(barbase + barn, bid);

                // G2: z2 = tf32(swish(z1 @ W2^T + b2)),  128 tiles (8x16)
                gemm_tiles<64>(g_z1, 1024, g_W2t, b2, 1024, 1024, 128,
                               sm, smu,
                               [&](int r, int c, float v) {
                                   float sw = v / (1.f + __expf(-v));
                                   g_z2[(size_t)r * 1024 + c] = __uint_as_float(f2tf(sw));
                               });
                barn++; grid_bar(barbase + barn, bid);

                // G3: k = z2 @ W3^T + b3 with fused RK accumulation AND
                // construction of the next eval's A1 = tf32(h + c_next*dt*k).
                // BN=32 -> 128 tiles (8x16), tile == bid: CTA owns a fixed
                // 64x32 block of h/ks (same-CTA locality preserved).
                gemm_tiles<32>(g_z2, 1024, g_W3t, b3, H_, 1024, 128,
                               sm, smu,
                               [&](int r, int c, float v) {
                                   float t1 = ts[r * T_ + tt];
                                   float t0 = (tt == 0) ? ts[r * T_] : ts[r * T_ + tt - 1];
                                   float dt = (t1 - t0) * 0.25f;
                                   int off = r * H_ + c;
                                   float a1v;
                                   if (j == 0)      { g_ks[off] = v;        a1v = g_h[off] + 0.5f * dt * v; }
                                   else if (j == 1) { g_ks[off] += 2.f * v; a1v = g_h[off] + 0.5f * dt * v; }
                                   else if (j == 2) { g_ks[off] += 2.f * v; a1v = g_h[off] + dt * v; }
                                   else {
                                       float hn = g_h[off] + dt * (1.f / 6.f) * (g_ks[off] + v);
                                       g_h[off] = hn;
                                       a1v = hn;
                                   }
                                   g_a1[r * K1PAD + c] = __uint_as_float(f2tf(a1v));
                               });
                // t-column for the next eval (512 rows; CTAs 0-1 x 256 thr)
                if (bid < 2) {
                    int r = bid * NTHR + tid;
                    float t1 = ts[r * T_ + tt];
                    float t0 = (tt == 0) ? ts[r * T_] : ts[r * T_ + tt - 1];
                    float dt = (t1 - t0) * 0.25f;
                    float sn = (j < 2) ? ((float)s + 0.5f) : ((float)s + 1.f);
                    g_a1[r * K1PAD + 512] = __uint_as_float(f2tf(t0 + sn * dt));
                }
                barn++; grid_bar(barbase + barn, bid);
            }
        }

        // GRU: gh = h @ Whh^T + bhh  (A = a1 which holds tf32(h_ode))
        gemm_tiles<64>(g_a1, K1PAD, g_Whht, bhh, 1536, 512, (512 / BM) * (1536 / 64),
                       sm, smu,
                       [&](int r, int c, float v) { g_gh[(size_t)r * 1536 + c] = v; });
        barn++; grid_bar(barbase + barn, bid);

        // gate: partition matches G3 tile ownership (bid -> 64x32 block) so
        // g_h stays CTA-local. At the last step, write the h output region
        // of dout DIRECTLY from registers (validated in R7/R8).
        {
            int r0 = (bid >> 4) * 64, c0 = (bid & 15) * 32;
            for (int e = tid; e < 64 * 32; e += NTHR) {
                int r = r0 + (e >> 5), c = c0 + (e & 31);
                int off = r * H_ + c;
                size_t gio = ((size_t)(r * T_ + tt)) * 1536 + c;
                float ir  = __ldcg(&g_gi[gio]);
                float iz  = __ldcg(&g_gi[gio + 512]);
                float inn = __ldcg(&g_gi[gio + 1024]);
                size_t gho = (size_t)r * 1536 + c;
                float hr = __ldcg(&g_gh[gho]);
                float hz = __ldcg(&g_gh[gho + 512]);
                float hn = __ldcg(&g_gh[gho + 1024]);
                float hv = g_h[off];
                float rg = 1.f / (1.f + expf(-(ir + hr)));
                float zg = 1.f / (1.f + expf(-(iz + hz)));
                float ng = tanhf(inn + rg * hn);
                float h2 = (1.f - zg) * ng + zg * hv;
                g_h[off] = h2;
                g_a1[r * K1PAD + c] = __uint_as_float(f2tf(h2));
                if (tt == T_ - 1) dout[B_ * 128 + off] = h2;   // h output, direct
            }
        }
        if (bid < 2) {   // t-column for next time step: t0' = ts[:, tt]
            int r = bid * NTHR + tid;
            g_a1[r * K1PAD + 512] = __uint_as_float(f2tf(ts[r * T_ + tt]));
        }
        barn++; grid_bar(barbase + barn, bid);
    }

    // outputs: outs[-1] = h @ Wout^T + bout (reads a1 = tf32(h_final)).
    // c output (zeros) is handled by the prologue.
    gemm_tiles<64>(g_a1, K1PAD, g_Woutt, bout, 128, 512, (512 / BM) * (128 / 64),
                   sm, smu,
                   [&](int r, int c, float v) { dout[(size_t)r * 128 + c] = v; });
}

// ---------------- prologue: exactly 3 kernels so ode_persist is our launch
// #4 (== overall #6; ncu -s 5 -c 1 captures it — worked in R11/R12). --------
__global__ void prep_a(const float* __restrict__ x,  float* __restrict__ xt,
                       const float* __restrict__ Wih, float* __restrict__ wih,
                       const float* __restrict__ Whh, float* __restrict__ whh) {
    int i = blockIdx.x * blockDim.x + threadIdx.x;
    if (i < B_ * T_ * H_) xt[i]  = __uint_as_float(f2tf(x[i]));
    if (i < 1536 * H_)    wih[i] = __uint_as_float(f2tf(Wih[i]));
    if (i < 1536 * H_)    whh[i] = __uint_as_float(f2tf(Whh[i]));
}

__global__ void prep_b(const float* __restrict__ W2,  float* __restrict__ w2,
                       const float* __restrict__ W3,  float* __restrict__ w3,
                       const float* __restrict__ Wout, float* __restrict__ wout,
                       const float* __restrict__ W1,  float* __restrict__ w1p) {
    int i = blockIdx.x * blockDim.x + threadIdx.x;
    if (i < 1024 * 1024) w2[i]  = __uint_as_float(f2tf(W2[i]));
    if (i < H_ * 1024)   w3[i]  = __uint_as_float(f2tf(W3[i]));
    if (i < 128 * H_)    wout[i] = __uint_as_float(f2tf(Wout[i]));
    if (i < 1024 * K1PAD) {
        int r = i / K1PAD, c = i - r * K1PAD;
        w1p[i] = (c < H_ + 1) ? __uint_as_float(f2tf(W1[r * (H_ + 1) + c])) : 0.f;
    }
}

__global__ void prep_c(const float* __restrict__ ts, float* __restrict__ dout) {
    int i = blockIdx.x * blockDim.x + threadIdx.x;
    if (i < B_ * H_) {
        g_h[i] = 0.f;
        dout[B_ * 128 + B_ * H_ + i] = 0.f;   // c output: always zeros
    }
    if (i < B_ * K1PAD) {
        int r = i / K1PAD, c = i - r * K1PAD;
        g_a1[i] = (c == 512) ? __uint_as_float(f2tf(ts[r * T_])) : 0.f;
    }
}

// ---------------- driver ----------------
extern "C" void kernel_launch(void* const* d_in, const int* in_sizes, int n_in,
                              void* d_out, int out_size) {
    const float* x    = (const float*)d_in[0];
    const float* ts   = (const float*)d_in[1];
    const float* Wih  = (const float*)d_in[2];
    const float* Whh  = (const float*)d_in[3];
    const float* bih  = (const float*)d_in[4];
    const float* bhh  = (const float*)d_in[5];
    const float* Wout = (const float*)d_in[6];
    const float* bout = (const float*)d_in[7];
    const float* W1   = (const float*)d_in[8];
    const float* b1   = (const float*)d_in[9];
    const float* W2   = (const float*)d_in[10];
    const float* b2   = (const float*)d_in[11];
    const float* W3   = (const float*)d_in[12];
    const float* b3   = (const float*)d_in[13];
    float* dout = (float*)d_out;
    (void)in_sizes; (void)n_in; (void)out_size;

    float *p_xt, *p_wih, *p_whh, *p_w2, *p_w3, *p_wout, *p_w1p;
    cudaGetSymbolAddress((void**)&p_xt,   g_xt);
    cudaGetSymbolAddress((void**)&p_wih,  g_Wiht);
    cudaGetSymbolAddress((void**)&p_whh,  g_Whht);
    cudaGetSymbolAddress((void**)&p_w2,   g_W2t);
    cudaGetSymbolAddress((void**)&p_w3,   g_W3t);
    cudaGetSymbolAddress((void**)&p_wout, g_Woutt);
    cudaGetSymbolAddress((void**)&p_w1p,  g_W1p);

    cudaFuncSetAttribute(ode_persist,
                         cudaFuncAttributeMaxDynamicSharedMemorySize, SMEM_BYTES);
    cudaFuncSetAttribute(ode_persist,
                         cudaFuncAttributePreferredSharedMemoryCarveout, 100);

    prep_a<<<(B_ * T_ * H_ + 255) / 256, 256>>>(x, p_xt, Wih, p_wih, Whh, p_whh);
    prep_b<<<(1024 * 1024 + 255) / 256, 256>>>(W2, p_w2, W3, p_w3,
                                               Wout, p_wout, W1, p_w1p);
    prep_c<<<(B_ * K1PAD + 255) / 256, 256>>>(ts, dout);

    ode_persist<<<NCTA, NTHR, SMEM_BYTES>>>(ts, bih, bhh, b1, b2, b3, bout, dout);
}

// round 16
// speedup vs baseline: 1.5721x; 1.0988x over previous
#include <cuda_runtime.h>
#include <math.h>

#define B_    512
#define T_    8
#define H_    512
#define K1PAD 576                   // 512 + t-col + zero pad, divisible by 64
#define NCTA  128
#define NTHR  256

#define BM  64
#define BK  64
#define SST 68                      // 64 + 4 pad words (row stride 272B)
#define STAGES 4
#define STG_W ((BM + 64) * SST)     // 8704 words per stage (A then B)
#define SMEM_BYTES (STAGES * STG_W * 4)   // 139264

// ---------------- scratch (static device globals; no allocation) ----------------
__device__ float g_a1[B_ * K1PAD];        // ODE GEMM1 input, tf32 values
__device__ float g_z1[B_ * 1024];         // tf32 values
__device__ float g_z2[B_ * 1024];         // tf32 values
__device__ float g_ks[B_ * H_];           // RK weighted sum, fp32
__device__ float g_h [B_ * H_];           // hidden state, fp32
__device__ float g_gi[B_ * T_ * 1536];    // precomputed input gates, fp32
__device__ float g_gh[B_ * 1536];         // hidden gates, fp32
__device__ float g_W1p [1024 * K1PAD];    // weights, tf32 values
__device__ float g_W2t [1024 * 1024];
__device__ float g_W3t [H_ * 1024];
__device__ float g_Whht[1536 * H_];
__device__ float g_Wiht[1536 * H_];
__device__ float g_Woutt[128 * H_];
__device__ float g_xt[B_ * T_ * H_];      // x converted to tf32
__device__ unsigned g_grp[16 * 32];       // tree-barrier group counters, 128B apart
__device__ unsigned g_root;               // tree-barrier root counter
__device__ volatile unsigned g_gen;       // published generation

// ---------------- helpers ----------------
__device__ __forceinline__ unsigned f2tf(float f) {
    unsigned u;
    asm("cvt.rna.tf32.f32 %0, %1;" : "=r"(u) : "f"(f));
    return u;
}

__device__ __forceinline__ void mma8(float* c, const unsigned* a, const unsigned* b) {
    asm volatile(
        "mma.sync.aligned.m16n8k8.row.col.f32.tf32.tf32.f32 "
        "{%0,%1,%2,%3}, {%4,%5,%6,%7}, {%8,%9}, {%0,%1,%2,%3};"
        : "+f"(c[0]), "+f"(c[1]), "+f"(c[2]), "+f"(c[3])
        : "r"(a[0]), "r"(a[1]), "r"(a[2]), "r"(a[3]), "r"(b[0]), "r"(b[1]));
}

__device__ __forceinline__ void cpa16(unsigned d, const float* s) {
    asm volatile("cp.async.cg.shared.global [%0], [%1], 16;" :: "r"(d), "l"(s));
}
__device__ __forceinline__ void cpcommit() { asm volatile("cp.async.commit_group;"); }

// Two-level tree grid barrier for 128 CTAs: 16 groups of 8 (separate 128B
// lines -> parallel LTS slices), root collects 16. All counters MONOTONIC
// (no resets) -> replay-safe exactly like the validated R8 design.
__device__ __forceinline__ void grid_bar(unsigned target, int bid) {
    __syncthreads();
    __threadfence();
    __syncthreads();
    if (threadIdx.x == 0) {
        unsigned a = atomicAdd(&g_grp[(bid & 15) * 32], 1u);
        if ((a & 7u) == 7u) {                   // last arriver in this group of 8
            unsigned r = atomicAdd(&g_root, 1u);
            if ((r & 15u) == 15u) {             // last of the 16 groups
                __threadfence();
                g_gen = target;
            }
        }
        while ((int)(g_gen - target) < 0) __nanosleep(32);
        __threadfence();
    }
    __syncthreads();
}

// ---------------- GEMM phase (persistent-kernel device function) ----------------
// C-tile = A[M,K] @ Wt[N,K]^T + bias, operands already tf32 in gmem.
// 64xBN_ CTA tile (BN_ = 64 or 32), 256 threads = 8 warps:
//   BN_=64: 2 (row) x 4 (col) warps, each 32 rows x 16 cols
//   BN_=32: 4 (row) x 2 (col) warps, each 16 rows x 16 cols
// BK=64 chunks with a 4-stage cp.async pipeline (wait_group 2 -> 3 chunks in
// flight, ~3 chunk-times of latency cover). Scalar-LDS fragment loads
// (validated R8 pattern; k-accumulation order identical to prior rounds).
template<int BN_, typename F>
__device__ __forceinline__ void gemm_tiles(
    const float* __restrict__ A, int lda,
    const float* __restrict__ Wt,
    const float* __restrict__ bias,
    int N, int K, int ntiles,
    const unsigned* sm, unsigned smu, F epi)
{
    constexpr int NCOLW = BN_ / 16;       // 4 or 2
    constexpr int NROWW = 8 / NCOLW;      // 2 or 4
    constexpr int RSPAN = BM / NROWW;     // 32 or 16
    constexpr int MT    = RSPAN / 16;     // 2 or 1
    constexpr int AITER = (BM * BK) / (NTHR * 4);   // 4
    constexpr int BITER = (BN_ * BK) / (NTHR * 4);  // 4 or 2

    const int tid  = threadIdx.x;
    const int lane = tid & 31, warp = tid >> 5;
    const int wr = warp / NCOLW, wc = warp % NCOLW;
    const int g = lane >> 2, tg = lane & 3;
    const int ncol = N / BN_;
    const int nch  = K / BK;

    for (int tile = blockIdx.x; tile < ntiles; tile += NCTA) {
        const int row0 = (tile / ncol) * BM;
        const int col0 = (tile % ncol) * BN_;
        const float* Ab = A  + (size_t)row0 * lda;
        const float* Bb = Wt + (size_t)col0 * K;
        __syncthreads();   // previous tile's smem reads complete

        auto issue = [&](int ck, int st) {
            unsigned base = smu + (unsigned)(st * STG_W) * 4u;
            int k0 = ck * BK;
#pragma unroll
            for (int i = 0; i < AITER; i++) {  // A: 64x64 = 1024 float4
                int lin = tid + i * NTHR; int r = lin >> 4, c4 = (lin & 15) * 4;
                cpa16(base + (unsigned)(r * SST + c4) * 4u,
                      Ab + (size_t)r * lda + k0 + c4);
            }
#pragma unroll
            for (int i = 0; i < BITER; i++) {  // B: BN_x64 float4
                int lin = tid + i * NTHR; int r = lin >> 4, c4 = (lin & 15) * 4;
                cpa16(base + (unsigned)((BM + r) * SST + c4) * 4u,
                      Bb + (size_t)r * K + k0 + c4);
            }
        };

        // pipeline prologue: chunks 0..2 (always STAGES-1 = 3 commits)
        int fetch = 0;
#pragma unroll
        for (int p = 0; p < STAGES - 1; ++p) {
            if (p < nch) { issue(p, p); fetch++; }
            cpcommit();
        }

        float acc[2][2][4];
#pragma unroll
        for (int a = 0; a < 2; a++)
#pragma unroll
            for (int b = 0; b < 2; b++)
#pragma unroll
                for (int e = 0; e < 4; e++) acc[a][b][e] = 0.f;

        for (int ch = 0; ch < nch; ++ch) {
            // retire chunk ch; keep ch+1, ch+2 in flight
            asm volatile("cp.async.wait_group 2;" ::: "memory");
            __syncthreads();
            // issue ch+3 into buffer (ch+3)&3 == (ch-1)&3: its reads
            // finished at iteration ch-1, ordered by the sync above
            if (fetch < nch) { issue(fetch, fetch & (STAGES - 1)); fetch++; }
            cpcommit();     // always commit so pending count stays aligned

            const unsigned* a_ = sm + (ch & (STAGES - 1)) * STG_W;
            const unsigned* b_ = a_ + BM * SST;
#pragma unroll
            for (int ks = 0; ks < 8; ks++) {
                unsigned af[MT][4];
#pragma unroll
                for (int mt = 0; mt < MT; mt++) {
                    int r = wr * RSPAN + mt * 16 + g;
                    int base = r * SST + ks * 8 + tg;
                    af[mt][0] = a_[base];
                    af[mt][1] = a_[base + 8 * SST];
                    af[mt][2] = a_[base + 4];
                    af[mt][3] = a_[base + 8 * SST + 4];
                }
#pragma unroll
                for (int nt = 0; nt < 2; nt++) {
                    int n = wc * 16 + nt * 8 + g;
                    unsigned bf[2];
                    bf[0] = b_[n * SST + ks * 8 + tg];
                    bf[1] = b_[n * SST + ks * 8 + tg + 4];
#pragma unroll
                    for (int mt = 0; mt < MT; mt++)
                        mma8(acc[mt][nt], af[mt], bf);
                }
            }
        }

#pragma unroll
        for (int mt = 0; mt < MT; mt++)
#pragma unroll
            for (int nt = 0; nt < 2; nt++)
#pragma unroll
                for (int e = 0; e < 4; e++) {
                    int r = row0 + wr * RSPAN + mt * 16 + g + ((e >= 2) ? 8 : 0);
                    int c = col0 + wc * 16 + nt * 8 + tg * 2 + (e & 1);
                    epi(r, c, acc[mt][nt][e] + bias[c]);
                }
    }
}

// ---------------- the persistent kernel ----------------
__global__ void __launch_bounds__(NTHR, 1)
ode_persist(const float* __restrict__ ts,  const float* __restrict__ bih,
            const float* __restrict__ bhh, const float* __restrict__ b1,
            const float* __restrict__ b2,  const float* __restrict__ b3,
            const float* __restrict__ bout, float* __restrict__ dout)
{
    extern __shared__ unsigned smem[];
    const unsigned smu = (unsigned)__cvta_generic_to_shared(smem);
    const unsigned* sm = smem;
    const int tid = threadIdx.x, bid = blockIdx.x;

    unsigned barn = 0, barbase = 0;
    if (tid == 0) barbase = g_gen;   // stable: cannot advance before all CTAs arrive at bar 1

    // ---- phase 0: gi = x @ Wih^T + bih (all 8 steps at once) ----
    gemm_tiles<64>(g_xt, 512, g_Wiht, bih, 1536, 512, (4096 / BM) * (1536 / 64),
                   sm, smu,
                   [&](int r, int c, float v) { g_gi[(size_t)r * 1536 + c] = v; });
    barn++; grid_bar(barbase + barn, bid);

    for (int tt = 0; tt < T_; tt++) {
        for (int s = 0; s < 4; s++) {
            for (int j = 0; j < 4; j++) {
                // G1: z1 = tf32(swish(a1 @ W1p^T + b1)),  128 tiles (8x16)
                gemm_tiles<64>(g_a1, K1PAD, g_W1p, b1, 1024, K1PAD, 128,
                               sm, smu,
                               [&](int r, int c, float v) {
                                   float sw = v / (1.f + __expf(-v));
                                   g_z1[(size_t)r * 1024 + c] = __uint_as_float(f2tf(sw));
                               });
                barn++; grid_bar(barbase + barn, bid);

                // G2: z2 = tf32(swish(z1 @ W2^T + b2)),  128 tiles (8x16)
                gemm_tiles<64>(g_z1, 1024, g_W2t, b2, 1024, 1024, 128,
                               sm, smu,
                               [&](int r, int c, float v) {
                                   float sw = v / (1.f + __expf(-v));
                                   g_z2[(size_t)r * 1024 + c] = __uint_as_float(f2tf(sw));
                               });
                barn++; grid_bar(barbase + barn, bid);

                // G3: k = z2 @ W3^T + b3 with fused RK accumulation AND
                // construction of the next eval's A1 = tf32(h + c_next*dt*k).
                // BN=32 -> 128 tiles (8x16), tile == bid: CTA owns a fixed
                // 64x32 block of h/ks (same-CTA locality preserved).
                gemm_tiles<32>(g_z2, 1024, g_W3t, b3, H_, 1024, 128,
                               sm, smu,
                               [&](int r, int c, float v) {
                                   float t1 = ts[r * T_ + tt];
                                   float t0 = (tt == 0) ? ts[r * T_] : ts[r * T_ + tt - 1];
                                   float dt = (t1 - t0) * 0.25f;
                                   int off = r * H_ + c;
                                   float a1v;
                                   if (j == 0)      { g_ks[off] = v;        a1v = g_h[off] + 0.5f * dt * v; }
                                   else if (j == 1) { g_ks[off] += 2.f * v; a1v = g_h[off] + 0.5f * dt * v; }
                                   else if (j == 2) { g_ks[off] += 2.f * v; a1v = g_h[off] + dt * v; }
                                   else {
                                       float hn = g_h[off] + dt * (1.f / 6.f) * (g_ks[off] + v);
                                       g_h[off] = hn;
                                       a1v = hn;
                                   }
                                   g_a1[r * K1PAD + c] = __uint_as_float(f2tf(a1v));
                               });
                // t-column for the next eval (512 rows; CTAs 0-1 x 256 thr)
                if (bid < 2) {
                    int r = bid * NTHR + tid;
                    float t1 = ts[r * T_ + tt];
                    float t0 = (tt == 0) ? ts[r * T_] : ts[r * T_ + tt - 1];
                    float dt = (t1 - t0) * 0.25f;
                    float sn = (j < 2) ? ((float)s + 0.5f) : ((float)s + 1.f);
                    g_a1[r * K1PAD + 512] = __uint_as_float(f2tf(t0 + sn * dt));
                }
                barn++; grid_bar(barbase + barn, bid);
            }
        }

        // GRU: gh = h @ Whh^T + bhh  (A = a1 which holds tf32(h_ode))
        gemm_tiles<64>(g_a1, K1PAD, g_Whht, bhh, 1536, 512, (512 / BM) * (1536 / 64),
                       sm, smu,
                       [&](int r, int c, float v) { g_gh[(size_t)r * 1536 + c] = v; });
        barn++; grid_bar(barbase + barn, bid);

        // gate: partition matches G3 tile ownership (bid -> 64x32 block) so
        // g_h stays CTA-local. At the last step, write the h output region
        // of dout DIRECTLY from registers (validated in R7/R8).
        {
            int r0 = (bid >> 4) * 64, c0 = (bid & 15) * 32;
            for (int e = tid; e < 64 * 32; e += NTHR) {
                int r = r0 + (e >> 5), c = c0 + (e & 31);
                int off = r * H_ + c;
                size_t gio = ((size_t)(r * T_ + tt)) * 1536 + c;
                float ir  = __ldcg(&g_gi[gio]);
                float iz  = __ldcg(&g_gi[gio + 512]);
                float inn = __ldcg(&g_gi[gio + 1024]);
                size_t gho = (size_t)r * 1536 + c;
                float hr = __ldcg(&g_gh[gho]);
                float hz = __ldcg(&g_gh[gho + 512]);
                float hn = __ldcg(&g_gh[gho + 1024]);
                float hv = g_h[off];
                float rg = 1.f / (1.f + expf(-(ir + hr)));
                float zg = 1.f / (1.f + expf(-(iz + hz)));
                float ng = tanhf(inn + rg * hn);
                float h2 = (1.f - zg) * ng + zg * hv;
                g_h[off] = h2;
                g_a1[r * K1PAD + c] = __uint_as_float(f2tf(h2));
                if (tt == T_ - 1) dout[B_ * 128 + off] = h2;   // h output, direct
            }
        }
        if (bid < 2) {   // t-column for next time step: t0' = ts[:, tt]
            int r = bid * NTHR + tid;
            g_a1[r * K1PAD + 512] = __uint_as_float(f2tf(ts[r * T_ + tt]));
        }
        barn++; grid_bar(barbase + barn, bid);
    }

    // outputs: outs[-1] = h @ Wout^T + bout (reads a1 = tf32(h_final)).
    // c output (zeros) is handled by the prologue.
    gemm_tiles<64>(g_a1, K1PAD, g_Woutt, bout, 128, 512, (512 / BM) * (128 / 64),
                   sm, smu,
                   [&](int r, int c, float v) { dout[(size_t)r * 128 + c] = v; });
}

// ---------------- prologue: exactly 3 kernels so ode_persist is our launch
// #4 (== overall #6; ncu -s 5 -c 1 captures it — worked in R11-R13). --------
__global__ void prep_a(const float* __restrict__ x,  float* __restrict__ xt,
                       const float* __restrict__ Wih, float* __restrict__ wih,
                       const float* __restrict__ Whh, float* __restrict__ whh) {
    int i = blockIdx.x * blockDim.x + threadIdx.x;
    if (i < B_ * T_ * H_) xt[i]  = __uint_as_float(f2tf(x[i]));
    if (i < 1536 * H_)    wih[i] = __uint_as_float(f2tf(Wih[i]));
    if (i < 1536 * H_)    whh[i] = __uint_as_float(f2tf(Whh[i]));
}

__global__ void prep_b(const float* __restrict__ W2,  float* __restrict__ w2,
                       const float* __restrict__ W3,  float* __restrict__ w3,
                       const float* __restrict__ Wout, float* __restrict__ wout,
                       const float* __restrict__ W1,  float* __restrict__ w1p) {
    int i = blockIdx.x * blockDim.x + threadIdx.x;
    if (i < 1024 * 1024) w2[i]  = __uint_as_float(f2tf(W2[i]));      // needs 4096 blocks
    if (i < H_ * 1024)   w3[i]  = __uint_as_float(f2tf(W3[i]));
    if (i < 128 * H_)    wout[i] = __uint_as_float(f2tf(Wout[i]));
    if (i < 1024 * K1PAD) {
        int r = i / K1PAD, c = i - r * K1PAD;
        w1p[i] = (c < H_ + 1) ? __uint_as_float(f2tf(W1[r * (H_ + 1) + c])) : 0.f;
    }
}

__global__ void prep_c(const float* __restrict__ ts, float* __restrict__ dout) {
    int i = blockIdx.x * blockDim.x + threadIdx.x;
    if (i < B_ * H_) {
        g_h[i] = 0.f;
        dout[B_ * 128 + B_ * H_ + i] = 0.f;   // c output: always zeros
    }
    if (i < B_ * K1PAD) {
        int r = i / K1PAD, c = i - r * K1PAD;
        g_a1[i] = (c == 512) ? __uint_as_float(f2tf(ts[r * T_])) : 0.f;
    }
}

// ---------------- driver ----------------
extern "C" void kernel_launch(void* const* d_in, const int* in_sizes, int n_in,
                              void* d_out, int out_size) {
    const float* x    = (const float*)d_in[0];
    const float* ts   = (const float*)d_in[1];
    const float* Wih  = (const float*)d_in[2];
    const float* Whh  = (const float*)d_in[3];
    const float* bih  = (const float*)d_in[4];
    const float* bhh  = (const float*)d_in[5];
    const float* Wout = (const float*)d_in[6];
    const float* bout = (const float*)d_in[7];
    const float* W1   = (const float*)d_in[8];
    const float* b1   = (const float*)d_in[9];
    const float* W2   = (const float*)d_in[10];
    const float* b2   = (const float*)d_in[11];
    const float* W3   = (const float*)d_in[12];
    const float* b3   = (const float*)d_in[13];
    float* dout = (float*)d_out;
    (void)in_sizes; (void)n_in; (void)out_size;

    float *p_xt, *p_wih, *p_whh, *p_w2, *p_w3, *p_wout, *p_w1p;
    cudaGetSymbolAddress((void**)&p_xt,   g_xt);
    cudaGetSymbolAddress((void**)&p_wih,  g_Wiht);
    cudaGetSymbolAddress((void**)&p_whh,  g_Whht);
    cudaGetSymbolAddress((void**)&p_w2,   g_W2t);
    cudaGetSymbolAddress((void**)&p_w3,   g_W3t);
    cudaGetSymbolAddress((void**)&p_wout, g_Woutt);
    cudaGetSymbolAddress((void**)&p_w1p,  g_W1p);

    cudaFuncSetAttribute(ode_persist,
                         cudaFuncAttributeMaxDynamicSharedMemorySize, SMEM_BYTES);
    cudaFuncSetAttribute(ode_persist,
                         cudaFuncAttributePreferredSharedMemoryCarveout, 100);

    prep_a<<<(B_ * T_ * H_ + 255) / 256, 256>>>(x, p_xt, Wih, p_wih, Whh, p_whh);
    // grid MUST cover the largest target (W2: 1024*1024) — R14's failure was
    // sizing this by 1024*K1PAD, leaving 44% of g_W2t unconverted (zeros).
    prep_b<<<(1024 * 1024 + 255) / 256, 256>>>(W2, p_w2, W3, p_w3,
                                               Wout, p_wout, W1, p_w1p);
    prep_c<<<(B_ * K1PAD + 255) / 256, 256>>>(ts, dout);

    ode_persist<<<NCTA, NTHR, SMEM_BYTES>>>(ts, bih, bhh, b1, b2, b3, bout, dout);
}